// round 12
// baseline (speedup 1.0000x reference)
#include <cuda_runtime.h>
#include <cuda_bf16.h>

// AttentionAggregator: out[n] = softmax_k(feats[n,k]·w) weighted sum of feats[n,k]
// feats[n,k] = embed_table[neigh_idx[n,k]]  (gather, D=128, K=10)
//
// R12: DRAM-traffic-bound (dur == 232MB / 4.05TB/s, invariant to shape).
// Pin the 102MB table in the 126MB L2 via ld.global.nc.L2::evict_last —
// which on sm_103a REQUIRES 256-bit loads (.v8.b32). So: half-warp per row,
// lane owns 8 dims (32B), one LDG.256 loads TWO gather rows (lanes 0-15 ->
// row 2c, lanes 16-31 -> row 2c+1). Output streamed with __stcs.

#define K_NEIGH 10
#define D_DIM   128

__device__ __forceinline__ void ldg_el_256(const float* p, float* v) {
    unsigned u0,u1,u2,u3,u4,u5,u6,u7;
    asm volatile("ld.global.nc.L2::evict_last.v8.b32 {%0,%1,%2,%3,%4,%5,%6,%7}, [%8];"
                 : "=r"(u0),"=r"(u1),"=r"(u2),"=r"(u3),
                   "=r"(u4),"=r"(u5),"=r"(u6),"=r"(u7)
                 : "l"(p));
    v[0]=__uint_as_float(u0); v[1]=__uint_as_float(u1);
    v[2]=__uint_as_float(u2); v[3]=__uint_as_float(u3);
    v[4]=__uint_as_float(u4); v[5]=__uint_as_float(u5);
    v[6]=__uint_as_float(u6); v[7]=__uint_as_float(u7);
}

__global__ __launch_bounds__(256) void attn_agg_kernel(
    const float* __restrict__ table,   // [VOCAB, 128]
    const float* __restrict__ attn_w,  // [128]
    const int*  __restrict__ nidx,     // [N, 10] (int32)
    float* __restrict__ out,           // [N, 128]
    int n_nodes)
{
    int warp = (int)((blockIdx.x * (unsigned)blockDim.x + threadIdx.x) >> 5);
    int lane = threadIdx.x & 31;
    if (warp >= n_nodes) return;

    int h  = lane >> 4;      // half-warp id: row parity
    int sl = lane & 15;      // sublane: owns dims [8*sl, 8*sl+8)

    // attn_w slice for this lane's 8 dims
    float w8[8];
    {
        float4 a = __ldg(reinterpret_cast<const float4*>(attn_w + sl * 8));
        float4 b = __ldg(reinterpret_cast<const float4*>(attn_w + sl * 8) + 1);
        w8[0]=a.x; w8[1]=a.y; w8[2]=a.z; w8[3]=a.w;
        w8[4]=b.x; w8[5]=b.y; w8[6]=b.z; w8[7]=b.w;
    }

    const int* ni = nidx + (long long)warp * K_NEIGH;

    float f[5][8];
    float sc[5];

    // 5 LDG.256: each loads two rows (row 2c for half 0, row 2c+1 for half 1).
    #pragma unroll
    for (int c = 0; c < 5; c++) {
        long long row = (long long)__ldg(ni + 2 * c + h);  // half-warp uniform
        ldg_el_256(table + row * D_DIM + sl * 8, f[c]);
    }

    // Scores: partial over 8 dims, reduce across the 16-lane half.
    #pragma unroll
    for (int c = 0; c < 5; c++) {
        float p = 0.f;
        #pragma unroll
        for (int d = 0; d < 8; d++) p = fmaf(f[c][d], w8[d], p);
        p += __shfl_xor_sync(0xffffffffu, p, 8);
        p += __shfl_xor_sync(0xffffffffu, p, 4);
        p += __shfl_xor_sync(0xffffffffu, p, 2);
        p += __shfl_xor_sync(0xffffffffu, p, 1);
        sc[c] = p;   // score of row 2c+h, identical across the 16-lane half
    }

    // Exchange with the other half -> all 10 scores everywhere.
    float s10[K_NEIGH];
    #pragma unroll
    for (int c = 0; c < 5; c++) {
        float so = __shfl_xor_sync(0xffffffffu, sc[c], 16);  // row 2c+(1-h)
        s10[2 * c + h]       = sc[c];
        s10[2 * c + (1 - h)] = so;
    }

    // softmax over K (identical in every lane)
    float m = s10[0];
    #pragma unroll
    for (int k = 1; k < K_NEIGH; k++) m = fmaxf(m, s10[k]);
    float sum = 0.f;
    #pragma unroll
    for (int k = 0; k < K_NEIGH; k++) { s10[k] = __expf(s10[k] - m); sum += s10[k]; }
    float inv = __frcp_rn(sum);

    // Weighted sum over this half's 5 rows, then cross-half combine.
    float acc[8] = {0,0,0,0,0,0,0,0};
    #pragma unroll
    for (int c = 0; c < 5; c++) {
        float wk = s10[2 * c + h] * inv;
        #pragma unroll
        for (int d = 0; d < 8; d++) acc[d] = fmaf(wk, f[c][d], acc[d]);
    }
    #pragma unroll
    for (int d = 0; d < 8; d++)
        acc[d] += __shfl_xor_sync(0xffffffffu, acc[d], 16);

    // Store: lane (h,sl) writes dims 8*sl + 4*h .. +3 -> warp covers the 512B row.
    float4 o = make_float4(acc[4*h+0], acc[4*h+1], acc[4*h+2], acc[4*h+3]);
    __stcs(reinterpret_cast<float4*>(out + (long long)warp * D_DIM + sl * 8 + 4 * h), o);
}

extern "C" void kernel_launch(void* const* d_in, const int* in_sizes, int n_in,
                              void* d_out, int out_size)
{
    const float* table  = (const float*)d_in[0];  // [VOCAB*128]
    const float* attn_w = (const float*)d_in[1];  // [128]
    const int*   nidx   = (const int*)d_in[2];    // [N*10] int32

    int n_nodes = in_sizes[2] / K_NEIGH;
    float* out = (float*)d_out;

    const int threads = 256;               // 8 warps -> 8 nodes per block
    int blocks = (n_nodes + 7) / 8;
    attn_agg_kernel<<<blocks, threads>>>(table, attn_w, nidx, out, n_nodes);
}

// round 15
// speedup vs baseline: 1.9583x; 1.9583x over previous
#include <cuda_runtime.h>
#include <cuda_bf16.h>
#include <cstdint>

// AttentionAggregator: out[n] = softmax_k(feats[n,k]·w) weighted sum of feats[n,k]
// feats[n,k] = embed_table[neigh_idx[n,k]]  (gather, D=128, K=10)
//
// R13: gather via cp.async.bulk (TMA/bulk path, GMEM->SMEM, bypasses the LDG
// register-return pipeline). Tests whether the invariant ~36.5us of L1tex
// wavefront time (constant across R3-R12) is the real limiter (H2) vs a
// ~4TB/s random-512B DRAM ceiling (H1). One warp per node; lane0 issues 10
// 512B bulk copies into a per-warp smem slab; mbarrier completion; compute
// from smem into registers; __stcs streaming store.

#define K_NEIGH 10
#define D_DIM   128
#define WARPS_PER_BLOCK 8
#define ROW_BYTES (D_DIM * 4)          // 512
#define SLAB_FLOATS (K_NEIGH * D_DIM)  // 1280 floats = 5120 B

__device__ __forceinline__ uint32_t smem_u32(const void* p) {
    uint32_t a;
    asm("{ .reg .u64 t; cvta.to.shared.u64 t, %1; cvt.u32.u64 %0, t; }"
        : "=r"(a) : "l"(p));
    return a;
}

__global__ __launch_bounds__(256) void attn_agg_kernel(
    const float* __restrict__ table,   // [VOCAB, 128]
    const float* __restrict__ attn_w,  // [128]
    const int*  __restrict__ nidx,     // [N, 10] (int32)
    float* __restrict__ out,           // [N, 128]
    int n_nodes)
{
    __shared__ __align__(16) float slab[WARPS_PER_BLOCK][SLAB_FLOATS];  // 40 KB
    __shared__ __align__(8)  unsigned long long mbar[WARPS_PER_BLOCK];

    int tid  = threadIdx.x;
    int wid  = tid >> 5;
    int lane = tid & 31;

    // init mbarriers (count=1: the single expect_tx arrival)
    if (tid < WARPS_PER_BLOCK) {
        uint32_t mb = smem_u32(&mbar[tid]);
        asm volatile("mbarrier.init.shared.b64 [%0], %1;" :: "r"(mb), "r"(1) : "memory");
    }
    __syncthreads();

    long long node = (long long)blockIdx.x * WARPS_PER_BLOCK + wid;
    if (node >= n_nodes) return;

    const float4 w4 = __ldg(reinterpret_cast<const float4*>(attn_w) + lane);

    const int* ni = nidx + node * K_NEIGH;
    int myidx = (lane < K_NEIGH) ? __ldg(ni + lane) : 0;

    uint32_t mb = smem_u32(&mbar[wid]);
    uint32_t slab_base = smem_u32(&slab[wid][0]);

    // lane 0: post expect_tx, then issue 10 independent 512B bulk copies
    if (lane == 0) {
        asm volatile("mbarrier.arrive.expect_tx.shared.b64 _, [%0], %1;"
                     :: "r"(mb), "r"((unsigned)(K_NEIGH * ROW_BYTES)) : "memory");
    }
    #pragma unroll
    for (int k = 0; k < K_NEIGH; k++) {
        long long row = (long long)__shfl_sync(0xffffffffu, myidx, k);
        if (lane == 0) {
            const float* src = table + row * D_DIM;
            asm volatile(
                "cp.async.bulk.shared::cta.global.mbarrier::complete_tx::bytes "
                "[%0], [%1], %2, [%3];"
                :: "r"(slab_base + k * ROW_BYTES), "l"(src),
                   "r"((unsigned)ROW_BYTES), "r"(mb)
                : "memory");
        }
    }

    // wait for all 5120 bytes (parity 0: single-shot barrier per launch)
    {
        uint32_t done;
        asm volatile(
            "{\n\t.reg .pred p;\n\t"
            "mbarrier.try_wait.parity.acquire.cta.shared::cta.b64 p, [%1], %2;\n\t"
            "selp.b32 %0, 1, 0, p;\n\t}"
            : "=r"(done) : "r"(mb), "r"(0) : "memory");
        if (!done) {
            asm volatile(
                "{\n\t.reg .pred P1;\n\t"
                "W_%=:\n\t"
                "mbarrier.try_wait.parity.acquire.cta.shared::cta.b64 P1, [%0], %1, 0x989680;\n\t"
                "@P1 bra.uni D_%=;\n\t"
                "bra.uni W_%=;\n\t"
                "D_%=:\n\t}"
                :: "r"(mb), "r"(0) : "memory");
        }
    }

    // pull rows smem -> registers (10x LDS.128 per lane)
    const float4* sp = reinterpret_cast<const float4*>(&slab[wid][0]);
    float4 f[K_NEIGH];
    #pragma unroll
    for (int k = 0; k < K_NEIGH; k++) f[k] = sp[k * 32 + lane];

    float s[K_NEIGH];
    #pragma unroll
    for (int k = 0; k < K_NEIGH; k++) {
        float p = f[k].x * w4.x + f[k].y * w4.y + f[k].z * w4.z + f[k].w * w4.w;
        p += __shfl_xor_sync(0xffffffffu, p, 16);
        p += __shfl_xor_sync(0xffffffffu, p, 8);
        p += __shfl_xor_sync(0xffffffffu, p, 4);
        p += __shfl_xor_sync(0xffffffffu, p, 2);
        p += __shfl_xor_sync(0xffffffffu, p, 1);
        s[k] = p;
    }

    float m = s[0];
    #pragma unroll
    for (int k = 1; k < K_NEIGH; k++) m = fmaxf(m, s[k]);
    float sum = 0.0f;
    #pragma unroll
    for (int k = 0; k < K_NEIGH; k++) { s[k] = __expf(s[k] - m); sum += s[k]; }
    float inv = __frcp_rn(sum);

    float4 acc = make_float4(0.f, 0.f, 0.f, 0.f);
    #pragma unroll
    for (int k = 0; k < K_NEIGH; k++) {
        float wk = s[k] * inv;
        acc.x = fmaf(wk, f[k].x, acc.x);
        acc.y = fmaf(wk, f[k].y, acc.y);
        acc.z = fmaf(wk, f[k].z, acc.z);
        acc.w = fmaf(wk, f[k].w, acc.w);
    }

    __stcs(reinterpret_cast<float4*>(out + node * D_DIM) + lane, acc);
}

extern "C" void kernel_launch(void* const* d_in, const int* in_sizes, int n_in,
                              void* d_out, int out_size)
{
    const float* table  = (const float*)d_in[0];  // [VOCAB*128]
    const float* attn_w = (const float*)d_in[1];  // [128]
    const int*   nidx   = (const int*)d_in[2];    // [N*10] int32

    int n_nodes = in_sizes[2] / K_NEIGH;
    float* out = (float*)d_out;

    const int threads = 256;               // 8 warps -> 8 nodes per block
    int blocks = (n_nodes + WARPS_PER_BLOCK - 1) / WARPS_PER_BLOCK;
    attn_agg_kernel<<<blocks, threads>>>(table, attn_w, nidx, out, n_nodes);
}

// round 16
// speedup vs baseline: 2.4794x; 1.2661x over previous
#include <cuda_runtime.h>
#include <cuda_bf16.h>

// AttentionAggregator: out[n] = softmax_k(feats[n,k]·w) weighted sum of feats[n,k]
// feats[n,k] = embed_table[neigh_idx[n,k]]  (gather, D=128, K=10)
//
// R14: DRAM traffic is invariantly 232MB (= 157MB compulsory + 75MB table
// re-fetch churn: L2 working set 157MB > 126MB L2). Remove the output stream
// from L2 entirely with st.global.wt (write-through, no allocation) so the
// 102MB table fits and persists within AND across graph replays.
// Skeleton = R8 (best): one warp/node, f[10] float4, __ldcg gather.

#define K_NEIGH 10
#define D_DIM   128

__device__ __forceinline__ void stg_wt4(float4* p, float4 v) {
    asm volatile("st.global.wt.v4.f32 [%0], {%1,%2,%3,%4};"
                 :: "l"(p), "f"(v.x), "f"(v.y), "f"(v.z), "f"(v.w)
                 : "memory");
}

__global__ __launch_bounds__(256) void attn_agg_kernel(
    const float* __restrict__ table,   // [VOCAB, 128]
    const float* __restrict__ attn_w,  // [128]
    const int*  __restrict__ nidx,     // [N, 10] (int32)
    float* __restrict__ out,           // [N, 128]
    int n_nodes)
{
    int warp = (int)((blockIdx.x * (unsigned)blockDim.x + threadIdx.x) >> 5);
    int lane = threadIdx.x & 31;
    if (warp >= n_nodes) return;

    // attn_w slice for this lane's 4 dims
    const float4 w4 = __ldg(reinterpret_cast<const float4*>(attn_w) + lane);

    const int* ni = nidx + (long long)warp * K_NEIGH;

    float4 f[K_NEIGH];
    float  s[K_NEIGH];

    // Issue all 10 independent row gathers (MLP=10), L1-bypassed (L2-only).
    #pragma unroll
    for (int k = 0; k < K_NEIGH; k++) {
        long long row = (long long)__ldg(ni + k);   // uniform broadcast
        f[k] = __ldcg(reinterpret_cast<const float4*>(table + row * D_DIM) + lane);
    }

    #pragma unroll
    for (int k = 0; k < K_NEIGH; k++) {
        float p = f[k].x * w4.x + f[k].y * w4.y + f[k].z * w4.z + f[k].w * w4.w;
        p += __shfl_xor_sync(0xffffffffu, p, 16);
        p += __shfl_xor_sync(0xffffffffu, p, 8);
        p += __shfl_xor_sync(0xffffffffu, p, 4);
        p += __shfl_xor_sync(0xffffffffu, p, 2);
        p += __shfl_xor_sync(0xffffffffu, p, 1);
        s[k] = p;
    }

    // softmax over K in registers
    float m = s[0];
    #pragma unroll
    for (int k = 1; k < K_NEIGH; k++) m = fmaxf(m, s[k]);
    float sum = 0.0f;
    #pragma unroll
    for (int k = 0; k < K_NEIGH; k++) { s[k] = __expf(s[k] - m); sum += s[k]; }
    float inv = __frcp_rn(sum);

    // weighted sum of register-resident feats
    float4 acc = make_float4(0.f, 0.f, 0.f, 0.f);
    #pragma unroll
    for (int k = 0; k < K_NEIGH; k++) {
        float wk = s[k] * inv;
        acc.x = fmaf(wk, f[k].x, acc.x);
        acc.y = fmaf(wk, f[k].y, acc.y);
        acc.z = fmaf(wk, f[k].z, acc.z);
        acc.w = fmaf(wk, f[k].w, acc.w);
    }

    // Write-through store: output must not occupy L2 (keep the table resident).
    stg_wt4(reinterpret_cast<float4*>(out + (long long)warp * D_DIM) + lane, acc);
}

extern "C" void kernel_launch(void* const* d_in, const int* in_sizes, int n_in,
                              void* d_out, int out_size)
{
    const float* table  = (const float*)d_in[0];  // [VOCAB*128]
    const float* attn_w = (const float*)d_in[1];  // [128]
    const int*   nidx   = (const int*)d_in[2];    // [N*10] int32

    int n_nodes = in_sizes[2] / K_NEIGH;
    float* out = (float*)d_out;

    const int threads = 256;               // 8 warps -> 8 nodes per block
    int blocks = (n_nodes + 7) / 8;
    attn_agg_kernel<<<blocks, threads>>>(table, attn_w, nidx, out, n_nodes);
}